// round 2
// baseline (speedup 1.0000x reference)
#include <cuda_runtime.h>
#include <math.h>

#define BS 256
#define T_ 128
#define HID 256
#define G3 768
#define NB 128
#define Y_OFF 8388608
#define R_OFF 8388864
#define A_OFF 16777472
#define L_OFF 16777728

typedef unsigned long long ull;
union F2 { ull u; float2 f; };
#define FMA2(a,x,y) asm("fma.rn.f32x2 %0,%1,%2,%0;" : "+l"(a) : "l"(x), "l"(y))
__device__ __forceinline__ ull pack2(float v){ ull r; asm("mov.b64 %0,{%1,%1};" : "=l"(r) : "f"(v)); return r; }

__device__ float g_GI0[BS*T_*G3];
__device__ float g_gh1[BS*G3];
__device__ float g_h1[2][BS*HID];
__device__ float g_h2[BS*HID];
__device__ float g_WC[BS*T_*HID];
__device__ float g_G[BS*T_*HID];
__device__ float g_yg[BS*HID];
__device__ float g_part[(T_-1)*BS];
__device__ unsigned g_cnt;
__device__ unsigned g_gen;

__device__ __forceinline__ float sigm(float x){ return 1.f/(1.f+expf(-x)); }
__device__ __forceinline__ float gelu_f(float x){ return 0.5f*x*(1.f+erff(x*0.70710678118654752f)); }

__device__ __forceinline__ void gbar(){
  __syncthreads();
  if (threadIdx.x==0){
    __threadfence();
    unsigned g = *(volatile unsigned*)&g_gen;
    if (atomicAdd(&g_cnt,1u)==NB-1u){
      g_cnt = 0u;
      __threadfence();
      atomicAdd(&g_gen,1u);
    } else {
      while (*(volatile unsigned*)&g_gen == g) __nanosleep(64);
      __threadfence();
    }
  }
  __syncthreads();
}

// ---------------- generic GEMM: C[M x N] = act(A[M x K=256](lda) @ B[N x 256]^T + bias) ----
__global__ void __launch_bounds__(256) gemm_bt(
    const float* __restrict__ A, int lda,
    const float* __restrict__ B,
    const float* __restrict__ bias,
    float* __restrict__ C, int ldc, int act)
{
  __shared__ float sAT[32][66];
  __shared__ ull sB2[64][33];
  const int bm = blockIdx.y*64, bn = blockIdx.x*64;
  const int tid = threadIdx.x;
  const int tx = tid & 15, ty = tid >> 4;
  const int lr = tid >> 3, lk = (tid & 7)*4;
  ull acc[4][2];
  #pragma unroll
  for (int c=0;c<4;c++){ acc[c][0]=0ull; acc[c][1]=0ull; }
  for (int kc=0;kc<256;kc+=32){
    __syncthreads();
    {
      float4 a0 = *(const float4*)(A + (size_t)(bm+lr)*lda + kc + lk);
      float4 a1 = *(const float4*)(A + (size_t)(bm+lr+32)*lda + kc + lk);
      float4 b0 = *(const float4*)(B + (size_t)(bn+lr)*256 + kc + lk);
      float4 b1 = *(const float4*)(B + (size_t)(bn+lr+32)*256 + kc + lk);
      sAT[lk+0][lr]=a0.x; sAT[lk+1][lr]=a0.y; sAT[lk+2][lr]=a0.z; sAT[lk+3][lr]=a0.w;
      sAT[lk+0][lr+32]=a1.x; sAT[lk+1][lr+32]=a1.y; sAT[lk+2][lr+32]=a1.z; sAT[lk+3][lr+32]=a1.w;
      sB2[lr][lk+0]=pack2(b0.x); sB2[lr][lk+1]=pack2(b0.y); sB2[lr][lk+2]=pack2(b0.z); sB2[lr][lk+3]=pack2(b0.w);
      sB2[lr+32][lk+0]=pack2(b1.x); sB2[lr+32][lk+1]=pack2(b1.y); sB2[lr+32][lk+2]=pack2(b1.z); sB2[lr+32][lk+3]=pack2(b1.w);
    }
    __syncthreads();
    #pragma unroll
    for (int k=0;k<32;k++){
      ull a01 = *(const ull*)&sAT[k][ty*4];
      ull a23 = *(const ull*)&sAT[k][ty*4+2];
      #pragma unroll
      for (int c=0;c<4;c++){
        ull b = sB2[tx + 16*c][k];
        FMA2(acc[c][0], a01, b);
        FMA2(acc[c][1], a23, b);
      }
    }
  }
  #pragma unroll
  for (int c=0;c<4;c++){
    int col = bn + tx + 16*c;
    float bv = bias ? bias[col] : 0.f;
    #pragma unroll
    for (int p=0;p<2;p++){
      F2 v; v.u = acc[c][p];
      float o0 = v.f.x + bv, o1 = v.f.y + bv;
      if (act){ o0 = gelu_f(o0); o1 = gelu_f(o1); }
      size_t r0 = (size_t)(bm + ty*4 + 2*p);
      C[r0*ldc + col] = o0;
      C[(r0+1)*ldc + col] = o1;
    }
  }
}

// ---------------- persistent GRU ----------------
__global__ void __launch_bounds__(128,1) gru_kernel(
    const float* __restrict__ Whh0, const float* __restrict__ bhh0,
    const float* __restrict__ Wih1, const float* __restrict__ bih1,
    const float* __restrict__ Whh1, const float* __restrict__ bhh1,
    float* __restrict__ H)
{
  __shared__ float sAT[32][34];
  __shared__ ull sB2[96][33];
  const int cta = blockIdx.x, tid = threadIdx.x;
  const int wid = tid>>5, tx = tid&31;
  const int ct = cta & 7;
  const int rtA = (cta & 63) >> 3;
  const int rtB = cta >> 3;
  const int col = ct*32 + tx;
  const bool l0 = (cta < 64);

  const float* bA = l0 ? bhh0 : bhh1;
  const float bAr = bA[col], bAz = bA[256+col], bAn = bA[512+col];
  const float bBr = bih1[col], bBz = bih1[256+col], bBn = bih1[512+col];
  const float* WA = l0 ? Whh0 : Whh1;

  const int alr = tid>>2, alk = (tid&3)*8;   // phase A: A-tile loader
  const int plr = tid&15, plk = (tid>>4)*4;  // phase B: A-tile loader

  for (int i = cta*128 + tid; i < BS*HID; i += NB*128){ g_h1[0][i]=0.f; g_h2[i]=0.f; }
  gbar();

  int cur = 0;
  #pragma unroll 1
  for (int t=0; t<T_; ++t){
    // ===== phase A: 32 rows x 96 cols of h @ Whh^T =====
    {
      const float* Ain = l0 ? g_h1[cur] : g_h2;
      ull acc[3][4];
      #pragma unroll
      for (int g=0;g<3;g++){ acc[g][0]=0; acc[g][1]=0; acc[g][2]=0; acc[g][3]=0; }
      #pragma unroll 1
      for (int kc=0;kc<256;kc+=32){
        __syncthreads();
        {
          const float* ar = Ain + (rtA*32+alr)*256 + kc + alk;
          float4 v0=*(const float4*)ar, v1=*(const float4*)(ar+4);
          sAT[alk+0][alr]=v0.x; sAT[alk+1][alr]=v0.y; sAT[alk+2][alr]=v0.z; sAT[alk+3][alr]=v0.w;
          sAT[alk+4][alr]=v1.x; sAT[alk+5][alr]=v1.y; sAT[alk+6][alr]=v1.z; sAT[alk+7][alr]=v1.w;
          #pragma unroll
          for (int g=0; g<3; g++){
            const float* wr = WA + (g*256 + ct*32 + alr)*256 + kc + alk;
            float4 w0=*(const float4*)wr, w1=*(const float4*)(wr+4);
            ull* d=&sB2[g*32+alr][alk];
            d[0]=pack2(w0.x); d[1]=pack2(w0.y); d[2]=pack2(w0.z); d[3]=pack2(w0.w);
            d[4]=pack2(w1.x); d[5]=pack2(w1.y); d[6]=pack2(w1.z); d[7]=pack2(w1.w);
          }
        }
        __syncthreads();
        #pragma unroll
        for (int k=0;k<32;k++){
          ull a0=*(const ull*)&sAT[k][wid*8];
          ull a1=*(const ull*)&sAT[k][wid*8+2];
          ull a2=*(const ull*)&sAT[k][wid*8+4];
          ull a3=*(const ull*)&sAT[k][wid*8+6];
          #pragma unroll
          for (int g=0;g<3;g++){
            ull b=sB2[g*32+tx][k];
            FMA2(acc[g][0],a0,b); FMA2(acc[g][1],a1,b);
            FMA2(acc[g][2],a2,b); FMA2(acc[g][3],a3,b);
          }
        }
      }
      if (l0){
        #pragma unroll
        for (int j=0;j<4;j++){
          F2 vr,vz,vn; vr.u=acc[0][j]; vz.u=acc[1][j]; vn.u=acc[2][j];
          float fr[2]={vr.f.x,vr.f.y}, fz[2]={vz.f.x,vz.f.y}, fn[2]={vn.f.x,vn.f.y};
          #pragma unroll
          for (int h=0;h<2;h++){
            int b = rtA*32 + wid*8 + j*2 + h;
            const float* gi = g_GI0 + ((size_t)b*T_ + t)*G3;
            float r = sigm(gi[col] + fr[h] + bAr);
            float z = sigm(gi[256+col] + fz[h] + bAz);
            float n = tanhf(gi[512+col] + r*(fn[h]+bAn));
            float ho = g_h1[cur][b*HID+col];
            g_h1[cur^1][b*HID+col] = (1.f-z)*n + z*ho;
          }
        }
      } else {
        #pragma unroll
        for (int j=0;j<4;j++){
          F2 vr,vz,vn; vr.u=acc[0][j]; vz.u=acc[1][j]; vn.u=acc[2][j];
          float fr[2]={vr.f.x,vr.f.y}, fz[2]={vz.f.x,vz.f.y}, fn[2]={vn.f.x,vn.f.y};
          #pragma unroll
          for (int h=0;h<2;h++){
            int b = rtA*32 + wid*8 + j*2 + h;
            g_gh1[b*G3+col]     = fr[h]+bAr;
            g_gh1[b*G3+256+col] = fz[h]+bAz;
            g_gh1[b*G3+512+col] = fn[h]+bAn;
          }
        }
      }
    }
    gbar();
    // ===== phase B: 16 rows x 96 cols of h1' @ Wih1^T, layer-1 update =====
    {
      const float* Ain = g_h1[cur^1];
      ull acc[3][2];
      #pragma unroll
      for (int g=0;g<3;g++){ acc[g][0]=0; acc[g][1]=0; }
      #pragma unroll 1
      for (int kc=0;kc<256;kc+=32){
        __syncthreads();
        {
          float4 v = *(const float4*)(Ain + (rtB*16+plr)*256 + kc + plk);
          sAT[plk+0][plr]=v.x; sAT[plk+1][plr]=v.y; sAT[plk+2][plr]=v.z; sAT[plk+3][plr]=v.w;
          #pragma unroll
          for (int g=0; g<3; g++){
            const float* wr = Wih1 + (g*256 + ct*32 + alr)*256 + kc + alk;
            float4 w0=*(const float4*)wr, w1=*(const float4*)(wr+4);
            ull* d=&sB2[g*32+alr][alk];
            d[0]=pack2(w0.x); d[1]=pack2(w0.y); d[2]=pack2(w0.z); d[3]=pack2(w0.w);
            d[4]=pack2(w1.x); d[5]=pack2(w1.y); d[6]=pack2(w1.z); d[7]=pack2(w1.w);
          }
        }
        __syncthreads();
        #pragma unroll
        for (int k=0;k<32;k++){
          ull a0=*(const ull*)&sAT[k][wid*4];
          ull a1=*(const ull*)&sAT[k][wid*4+2];
          #pragma unroll
          for (int g=0;g<3;g++){
            ull b=sB2[g*32+tx][k];
            FMA2(acc[g][0],a0,b); FMA2(acc[g][1],a1,b);
          }
        }
      }
      #pragma unroll
      for (int j=0;j<2;j++){
        F2 vr,vz,vn; vr.u=acc[0][j]; vz.u=acc[1][j]; vn.u=acc[2][j];
        float fr[2]={vr.f.x,vr.f.y}, fz[2]={vz.f.x,vz.f.y}, fn[2]={vn.f.x,vn.f.y};
        #pragma unroll
        for (int h=0;h<2;h++){
          int b = rtB*16 + wid*4 + j*2 + h;
          const float* gh = g_gh1 + b*G3;
          float r = sigm(fr[h] + bBr + gh[col]);
          float z = sigm(fz[h] + bBz + gh[256+col]);
          float n = tanhf(fn[h] + bBn + r*gh[512+col]);
          float ho = g_h2[b*HID+col];
          float hn2 = (1.f-z)*n + z*ho;
          g_h2[b*HID+col] = hn2;
          H[((size_t)b*T_+t)*HID + col] = hn2;
        }
      }
    }
    gbar();
    cur ^= 1;
  }
}

// ---------------- small heads ----------------
__global__ void y_kernel(const float* __restrict__ Wp2, float* __restrict__ y){
  __shared__ float s[256];
  int b=blockIdx.x, tid=threadIdx.x;
  s[tid] = g_yg[b*256+tid]*Wp2[tid];
  __syncthreads();
  for (int o=128;o;o>>=1){ if(tid<o) s[tid]+=s[tid+o]; __syncthreads(); }
  if(!tid) y[b]=s[0];
}

__global__ void alpha_kernel(const float* __restrict__ P, float* __restrict__ alpha){
  __shared__ float s[256];
  int b=blockIdx.x, tid=threadIdx.x;
  s[tid] = g_WC[((size_t)b*T_+126)*256+tid] * P[((size_t)b*T_+127)*256+tid];
  __syncthreads();
  for (int o=128;o;o>>=1){ if(tid<o) s[tid]+=s[tid+o]; __syncthreads(); }
  if(!tid) alpha[b]=s[0]*(1.f/256.f);
}

__global__ void ce_kernel(const float* __restrict__ P, const int* __restrict__ neg){
  __shared__ float swc[256];
  __shared__ float red[16];
  int b=blockIdx.x, t=blockIdx.y, tid=threadIdx.x;
  int wid=tid>>5, lane=tid&31;
  const float* wc = g_WC + ((size_t)b*T_+t)*HID;
  for (int i=tid;i<256;i+=128) swc[i]=wc[i];
  __syncthreads();
  for (int j=wid;j<16;j+=4){
    int src = (j==0) ? b : neg[((size_t)t*15+(j-1))*BS + b];
    const float* p = P + ((size_t)src*T_ + t + 1)*256;
    float s=0.f;
    for (int d=lane; d<256; d+=32) s += swc[d]*p[d];
    #pragma unroll
    for (int o=16;o;o>>=1) s += __shfl_xor_sync(0xffffffffu, s, o);
    if (!lane) red[j] = s*(1.f/256.f);
  }
  __syncthreads();
  if (!tid){
    float m=red[0];
    #pragma unroll
    for (int j=1;j<16;j++) m=fmaxf(m,red[j]);
    float sum=0.f;
    #pragma unroll
    for (int j=0;j<16;j++) sum+=expf(red[j]-m);
    g_part[(size_t)t*BS+b] = m + logf(sum) - red[0];
  }
}

__global__ void loss_kernel(float* __restrict__ out){
  __shared__ float s[256];
  int tid=threadIdx.x;
  float a=0.f;
  for (int i=tid;i<(T_-1)*BS;i+=256) a+=g_part[i];
  s[tid]=a; __syncthreads();
  for (int o=128;o;o>>=1){ if(tid<o) s[tid]+=s[tid+o]; __syncthreads(); }
  if(!tid) out[0]=s[0]*(1.f/(float)BS);
}

extern "C" void kernel_launch(void* const* d_in, const int* in_sizes, int n_in,
                              void* d_out, int out_size){
  const float *P=(const float*)d_in[0], *Wih0=(const float*)d_in[1], *Whh0=(const float*)d_in[2],
              *bih0=(const float*)d_in[3], *bhh0=(const float*)d_in[4], *Wih1=(const float*)d_in[5],
              *Whh1=(const float*)d_in[6], *bih1=(const float*)d_in[7], *bhh1=(const float*)d_in[8],
              *W=(const float*)d_in[9],  *Wp1=(const float*)d_in[10], *Wp2=(const float*)d_in[11],
              *Wr1=(const float*)d_in[12], *Wr2=(const float*)d_in[13];
  const int* neg=(const int*)d_in[14];
  float* out=(float*)d_out;

  float *pGI0,*pWC,*pG,*pYG;
  cudaGetSymbolAddress((void**)&pGI0, g_GI0);
  cudaGetSymbolAddress((void**)&pWC,  g_WC);
  cudaGetSymbolAddress((void**)&pG,   g_G);
  cudaGetSymbolAddress((void**)&pYG,  g_yg);

  gemm_bt<<<dim3(G3/64, (BS*T_)/64), 256>>>(P, 256, Wih0, bih0, pGI0, G3, 0);
  gru_kernel<<<NB,128>>>(Whh0,bhh0,Wih1,bih1,Whh1,bhh1,out);
  gemm_bt<<<dim3(4, (BS*T_)/64), 256>>>(out, 256, W,   nullptr, pWC, 256, 0);
  gemm_bt<<<dim3(4, (BS*T_)/64), 256>>>(out, 256, Wr1, nullptr, pG,  256, 1);
  gemm_bt<<<dim3(4, (BS*T_)/64), 256>>>(pG,  256, Wr2, nullptr, out+R_OFF, 256, 0);
  gemm_bt<<<dim3(4, 4), 256>>>(out + 127*HID, T_*HID, Wp1, nullptr, pYG, 256, 1);
  y_kernel<<<BS,256>>>(Wp2, out+Y_OFF);
  alpha_kernel<<<BS,256>>>(P, out+A_OFF);
  ce_kernel<<<dim3(BS, T_-1), 128>>>(P, neg);
  loss_kernel<<<1,256>>>(out+L_OFF);
}

// round 3
// speedup vs baseline: 1.6697x; 1.6697x over previous
#include <cuda_runtime.h>
#include <math.h>

#define BS 256
#define T_ 128
#define HID 256
#define G3 768
#define NB 128
#define Y_OFF 8388608
#define R_OFF 8388864
#define A_OFF 16777472
#define L_OFF 16777728

typedef unsigned long long ull;
union F2 { ull u; float2 f; };
#define FMA2(a,x,y) asm("fma.rn.f32x2 %0,%1,%2,%0;" : "+l"(a) : "l"(x), "l"(y))
__device__ __forceinline__ ull pack2(float v){ ull r; asm("mov.b64 %0,{%1,%1};" : "=l"(r) : "f"(v)); return r; }

__device__ float g_GI0[BS*T_*G3];
__device__ float g_gi1[2][BS*G3];
__device__ float g_h1[2][BS*HID];
__device__ float g_h2[2][BS*HID];
__device__ float g_WC[BS*T_*HID];
__device__ float g_G[BS*T_*HID];
__device__ float g_yg[BS*HID];
__device__ float g_part[(T_-1)*BS];
__device__ unsigned g_cnt;
__device__ unsigned g_gen;

__device__ __forceinline__ float sigm(float x){ return 1.f/(1.f+expf(-x)); }
__device__ __forceinline__ float gelu_f(float x){ return 0.5f*x*(1.f+erff(x*0.70710678118654752f)); }

__device__ __forceinline__ void gbar(){
  __syncthreads();
  if (threadIdx.x==0){
    __threadfence();
    unsigned g = *(volatile unsigned*)&g_gen;
    if (atomicAdd(&g_cnt,1u)==NB-1u){
      g_cnt = 0u;
      __threadfence();
      atomicAdd(&g_gen,1u);
    } else {
      while (*(volatile unsigned*)&g_gen == g) __nanosleep(64);
      __threadfence();
    }
  }
  __syncthreads();
}

// ======== gemm128: C[M x N] = act(A[M x 256](lda) @ B[N x 256]^T + bias) =========
// CTA tile 128x128, 256 threads, thread tile 8 rows x 8 cols (cols strided 16)
__global__ void __launch_bounds__(256) gemm128(
    const float* __restrict__ A, int lda,
    const float* __restrict__ B,
    const float* __restrict__ bias,
    float* __restrict__ C, int ldc, int act)
{
  __shared__ float sA[32][130];
  __shared__ float sB[32][130];
  const int bm = blockIdx.y*128, bn = blockIdx.x*128;
  const int tid = threadIdx.x;
  const int rg = tid>>4, cg = tid&15;
  ull acc[8][4];
  #pragma unroll
  for (int j=0;j<8;j++){ acc[j][0]=0; acc[j][1]=0; acc[j][2]=0; acc[j][3]=0; }

  float4 pa[4], pb[4];
  #pragma unroll
  for (int i=0;i<4;i++){
    int idx = tid + 256*i; int row = idx>>3, kq = idx&7;
    pa[i] = *(const float4*)(A + (size_t)(bm+row)*lda + kq*4);
    pb[i] = *(const float4*)(B + (size_t)(bn+row)*256 + kq*4);
  }
  for (int kc=0; kc<256; kc+=32){
    __syncthreads();
    #pragma unroll
    for (int i=0;i<4;i++){
      int idx = tid + 256*i; int row = idx>>3, kq = idx&7;
      sA[kq*4+0][row]=pa[i].x; sA[kq*4+1][row]=pa[i].y; sA[kq*4+2][row]=pa[i].z; sA[kq*4+3][row]=pa[i].w;
      sB[kq*4+0][row]=pb[i].x; sB[kq*4+1][row]=pb[i].y; sB[kq*4+2][row]=pb[i].z; sB[kq*4+3][row]=pb[i].w;
    }
    __syncthreads();
    if (kc+32 < 256){
      #pragma unroll
      for (int i=0;i<4;i++){
        int idx = tid + 256*i; int row = idx>>3, kq = idx&7;
        pa[i] = *(const float4*)(A + (size_t)(bm+row)*lda + kc+32 + kq*4);
        pb[i] = *(const float4*)(B + (size_t)(bn+row)*256 + kc+32 + kq*4);
      }
    }
    #pragma unroll
    for (int k=0;k<32;k++){
      ull a0=*(const ull*)&sA[k][rg*8];
      ull a1=*(const ull*)&sA[k][rg*8+2];
      ull a2=*(const ull*)&sA[k][rg*8+4];
      ull a3=*(const ull*)&sA[k][rg*8+6];
      #pragma unroll
      for (int j=0;j<8;j++){
        ull bb = pack2(sB[k][cg+16*j]);
        FMA2(acc[j][0],a0,bb); FMA2(acc[j][1],a1,bb);
        FMA2(acc[j][2],a2,bb); FMA2(acc[j][3],a3,bb);
      }
    }
  }
  #pragma unroll
  for (int j=0;j<8;j++){
    int col = bn + cg + 16*j;
    float bv = bias ? bias[col] : 0.f;
    #pragma unroll
    for (int p=0;p<4;p++){
      F2 u; u.u = acc[j][p];
      float v[2] = {u.f.x, u.f.y};
      #pragma unroll
      for (int h=0;h<2;h++){
        float o = v[h] + bv;
        if (act) o = gelu_f(o);
        size_t r = (size_t)(bm + rg*8 + 2*p + h);
        C[r*ldc + col] = o;
      }
    }
  }
}

// ======== persistent GRU: 1 phase/step, 3 GEMM groups in parallel ========
// grp0: h1(p)@Whh0^T + layer0 update -> h1(p+1)     (p < 128)
// grp1: h1(p)@Wih1^T + bih1 -> gi1 buffer           (1 <= p <= 128)
// grp2: h2(p-2-state)@Whh1^T + layer1 update -> h2, H[:,p-2,:]  (p >= 2)
__global__ void __launch_bounds__(256,1) gru_kernel(
    const float* __restrict__ Whh0, const float* __restrict__ bhh0,
    const float* __restrict__ Wih1, const float* __restrict__ bih1,
    const float* __restrict__ Whh1, const float* __restrict__ bhh1,
    float* __restrict__ H)
{
  __shared__ float sA[32][66];
  __shared__ float sB[32][98];
  const int cta = blockIdx.x, tid = threadIdx.x;
  const int grp = cta>>5;        // 0..3 (3 = idle)
  const int loc = cta&31;
  const int rt = loc>>3, ct = loc&7;
  const int rg = tid>>4, tx = tid&15;
  const int row0 = rt*64 + rg*4;       // batch row base (4 rows)
  const int colp = ct*32 + tx*2;       // hidden col base (2 cols)
  const bool is0 = (grp==0), is1 = (grp==1), is2 = (grp==2);

  const float* WB = is0 ? Whh0 : (is1 ? Wih1 : Whh1);
  const float* bv = is0 ? bhh0 : (is1 ? bih1 : bhh1);
  float bR[2], bZ[2], bN[2];
  if (grp < 3){
    #pragma unroll
    for (int c=0;c<2;c++){
      bR[c]=bv[colp+c]; bZ[c]=bv[256+colp+c]; bN[c]=bv[512+colp+c];
    }
  }
  // loader indices
  const int alr = tid>>2, akq = tid&3;   // A: row 0..63, k-quad (and +4)
  const int blr = tid>>3, bkq = tid&7;   // B: row-in-gate 0..31, k-quad 0..7

  for (int i = cta*256 + tid; i < BS*HID; i += NB*256){
    g_h1[0][i] = 0.f; g_h2[1][i] = 0.f;
  }
  gbar();

  #pragma unroll 1
  for (int p=0; p<T_+2; ++p){
    bool active = (is0 && p<T_) || (is1 && p>=1 && p<=T_) || (is2 && p>=2);
    if (active){
      const float* Ain = is2 ? g_h2[(p-1)&1] : g_h1[p&1];
      ull acc[3][2][2];
      #pragma unroll
      for (int g=0;g<3;g++){ acc[g][0][0]=0; acc[g][0][1]=0; acc[g][1][0]=0; acc[g][1][1]=0; }

      float4 pa0 = *(const float4*)(Ain + (rt*64+alr)*256 + akq*4);
      float4 pa1 = *(const float4*)(Ain + (rt*64+alr)*256 + (akq+4)*4);
      float4 pw[3];
      #pragma unroll
      for (int g=0;g<3;g++)
        pw[g] = *(const float4*)(WB + (g*256 + ct*32 + blr)*256 + bkq*4);

      #pragma unroll 1
      for (int kc=0;kc<256;kc+=32){
        __syncthreads();
        sA[akq*4+0][alr]=pa0.x; sA[akq*4+1][alr]=pa0.y; sA[akq*4+2][alr]=pa0.z; sA[akq*4+3][alr]=pa0.w;
        sA[(akq+4)*4+0][alr]=pa1.x; sA[(akq+4)*4+1][alr]=pa1.y; sA[(akq+4)*4+2][alr]=pa1.z; sA[(akq+4)*4+3][alr]=pa1.w;
        #pragma unroll
        for (int g=0;g<3;g++){
          sB[bkq*4+0][g*32+blr]=pw[g].x; sB[bkq*4+1][g*32+blr]=pw[g].y;
          sB[bkq*4+2][g*32+blr]=pw[g].z; sB[bkq*4+3][g*32+blr]=pw[g].w;
        }
        __syncthreads();
        if (kc+32 < 256){
          pa0 = *(const float4*)(Ain + (rt*64+alr)*256 + kc+32 + akq*4);
          pa1 = *(const float4*)(Ain + (rt*64+alr)*256 + kc+32 + (akq+4)*4);
          #pragma unroll
          for (int g=0;g<3;g++)
            pw[g] = *(const float4*)(WB + (g*256 + ct*32 + blr)*256 + kc+32 + bkq*4);
        }
        #pragma unroll
        for (int k=0;k<32;k++){
          ull a0 = *(const ull*)&sA[k][rg*4];
          ull a1 = *(const ull*)&sA[k][rg*4+2];
          #pragma unroll
          for (int g=0;g<3;g++){
            F2 bf; bf.f = *(const float2*)&sB[k][g*32 + tx*2];
            ull b0 = pack2(bf.f.x), b1 = pack2(bf.f.y);
            FMA2(acc[g][0][0], a0, b0); FMA2(acc[g][0][1], a1, b0);
            FMA2(acc[g][1][0], a0, b1); FMA2(acc[g][1][1], a1, b1);
          }
        }
      }
      // ---- epilogue ----
      #pragma unroll
      for (int c=0;c<2;c++){
        int col = colp + c;
        #pragma unroll
        for (int pr=0;pr<2;pr++){
          F2 ur,uz,un;
          ur.u = acc[0][c][pr]; uz.u = acc[1][c][pr]; un.u = acc[2][c][pr];
          float fr[2]={ur.f.x,ur.f.y}, fz[2]={uz.f.x,uz.f.y}, fn[2]={un.f.x,un.f.y};
          #pragma unroll
          for (int h=0;h<2;h++){
            int b = row0 + pr*2 + h;
            if (is0){
              const float* gi = g_GI0 + ((size_t)b*T_ + p)*G3;
              float r = sigm(gi[col]     + fr[h] + bR[c]);
              float z = sigm(gi[256+col] + fz[h] + bZ[c]);
              float n = tanhf(gi[512+col] + r*(fn[h] + bN[c]));
              float ho = g_h1[p&1][b*HID+col];
              g_h1[(p+1)&1][b*HID+col] = (1.f-z)*n + z*ho;
            } else if (is1){
              float* o = g_gi1[p&1] + b*G3;
              o[col]     = fr[h] + bR[c];
              o[256+col] = fz[h] + bZ[c];
              o[512+col] = fn[h] + bN[c];
            } else {
              const float* gi = g_gi1[(p-1)&1] + b*G3;
              float r = sigm(gi[col]     + fr[h] + bR[c]);
              float z = sigm(gi[256+col] + fz[h] + bZ[c]);
              float n = tanhf(gi[512+col] + r*(fn[h] + bN[c]));
              float ho = g_h2[(p-1)&1][b*HID+col];
              float hn = (1.f-z)*n + z*ho;
              g_h2[p&1][b*HID+col] = hn;
              H[((size_t)b*T_ + (p-2))*HID + col] = hn;
            }
          }
        }
      }
    }
    gbar();
  }
}

// ---------------- small heads ----------------
__global__ void y_kernel(const float* __restrict__ Wp2, float* __restrict__ y){
  __shared__ float s[256];
  int b=blockIdx.x, tid=threadIdx.x;
  s[tid] = g_yg[b*256+tid]*Wp2[tid];
  __syncthreads();
  for (int o=128;o;o>>=1){ if(tid<o) s[tid]+=s[tid+o]; __syncthreads(); }
  if(!tid) y[b]=s[0];
}

__global__ void alpha_kernel(const float* __restrict__ P, float* __restrict__ alpha){
  __shared__ float s[256];
  int b=blockIdx.x, tid=threadIdx.x;
  s[tid] = g_WC[((size_t)b*T_+126)*256+tid] * P[((size_t)b*T_+127)*256+tid];
  __syncthreads();
  for (int o=128;o;o>>=1){ if(tid<o) s[tid]+=s[tid+o]; __syncthreads(); }
  if(!tid) alpha[b]=s[0]*(1.f/256.f);
}

__global__ void ce_kernel(const float* __restrict__ P, const int* __restrict__ neg){
  __shared__ float swc[256];
  __shared__ float red[16];
  int b=blockIdx.x, t=blockIdx.y, tid=threadIdx.x;
  int wid=tid>>5, lane=tid&31;
  const float* wc = g_WC + ((size_t)b*T_+t)*HID;
  for (int i=tid;i<256;i+=128) swc[i]=wc[i];
  __syncthreads();
  for (int j=wid;j<16;j+=4){
    int src = (j==0) ? b : neg[((size_t)t*15+(j-1))*BS + b];
    const float* p = P + ((size_t)src*T_ + t + 1)*256;
    float s=0.f;
    for (int d=lane; d<256; d+=32) s += swc[d]*p[d];
    #pragma unroll
    for (int o=16;o;o>>=1) s += __shfl_xor_sync(0xffffffffu, s, o);
    if (!lane) red[j] = s*(1.f/256.f);
  }
  __syncthreads();
  if (!tid){
    float m=red[0];
    #pragma unroll
    for (int j=1;j<16;j++) m=fmaxf(m,red[j]);
    float sum=0.f;
    #pragma unroll
    for (int j=0;j<16;j++) sum+=expf(red[j]-m);
    g_part[(size_t)t*BS+b] = m + logf(sum) - red[0];
  }
}

__global__ void loss_kernel(float* __restrict__ out){
  __shared__ float s[256];
  int tid=threadIdx.x;
  float a=0.f;
  for (int i=tid;i<(T_-1)*BS;i+=256) a+=g_part[i];
  s[tid]=a; __syncthreads();
  for (int o=128;o;o>>=1){ if(tid<o) s[tid]+=s[tid+o]; __syncthreads(); }
  if(!tid) out[0]=s[0]*(1.f/(float)BS);
}

extern "C" void kernel_launch(void* const* d_in, const int* in_sizes, int n_in,
                              void* d_out, int out_size){
  const float *P=(const float*)d_in[0], *Wih0=(const float*)d_in[1], *Whh0=(const float*)d_in[2],
              *bih0=(const float*)d_in[3], *bhh0=(const float*)d_in[4], *Wih1=(const float*)d_in[5],
              *Whh1=(const float*)d_in[6], *bih1=(const float*)d_in[7], *bhh1=(const float*)d_in[8],
              *W=(const float*)d_in[9],  *Wp1=(const float*)d_in[10], *Wp2=(const float*)d_in[11],
              *Wr1=(const float*)d_in[12], *Wr2=(const float*)d_in[13];
  const int* neg=(const int*)d_in[14];
  float* out=(float*)d_out;

  float *pGI0,*pWC,*pG,*pYG;
  cudaGetSymbolAddress((void**)&pGI0, g_GI0);
  cudaGetSymbolAddress((void**)&pWC,  g_WC);
  cudaGetSymbolAddress((void**)&pG,   g_G);
  cudaGetSymbolAddress((void**)&pYG,  g_yg);

  gemm128<<<dim3(G3/128, (BS*T_)/128), 256>>>(P, 256, Wih0, bih0, pGI0, G3, 0);
  gru_kernel<<<NB,256>>>(Whh0,bhh0,Wih1,bih1,Whh1,bhh1,out);
  gemm128<<<dim3(2, (BS*T_)/128), 256>>>(out, 256, W,   nullptr, pWC, 256, 0);
  gemm128<<<dim3(2, (BS*T_)/128), 256>>>(out, 256, Wr1, nullptr, pG,  256, 1);
  gemm128<<<dim3(2, (BS*T_)/128), 256>>>(pG,  256, Wr2, nullptr, out+R_OFF, 256, 0);
  gemm128<<<dim3(2, 2), 256>>>(out + 127*HID, T_*HID, Wp1, nullptr, pYG, 256, 1);
  y_kernel<<<BS,256>>>(Wp2, out+Y_OFF);
  alpha_kernel<<<BS,256>>>(P, out+A_OFF);
  ce_kernel<<<dim3(BS, T_-1), 128>>>(P, neg);
  loss_kernel<<<1,256>>>(out+L_OFF);
}